// round 6
// baseline (speedup 1.0000x reference)
#include <cuda_runtime.h>
#include <cuda_bf16.h>
#include <cuda_fp16.h>
#include <math.h>
#include <stdint.h>

#define B_   4
#define C_   256
#define D_   128
#define HW_  16384
#define W_   128
#define T_   16384
#define MAX_DELTA 0.0009765625f   // 0.5/512

// 8 MB scratch: projected feature map in fp8 e4m3, channel-last: vm[b][pix][d]
__device__ uint8_t g_vm8[(size_t)B_ * HW_ * D_];
// 16 MB scratch: sampled features fp16 [pt][d]
__device__ __half g_feat[(size_t)B_ * T_ * D_];
// 64 KB: Wp pre-converted to bf16 [d][c]
__device__ __nv_bfloat16 g_wp[D_ * C_];
// 32 KB: W1 pre-converted to fp16 [j][k]
__device__ __half g_w1h[D_ * D_];

// ---------------------------------------------------------------------------
// helpers
// ---------------------------------------------------------------------------
__device__ __forceinline__ uint32_t s2u(const void* p) {
    return (uint32_t)__cvta_generic_to_shared(p);
}
__device__ __forceinline__ void cp_async16(void* smem_dst, const void* gmem_src) {
    asm volatile("cp.async.cg.shared.global [%0], [%1], 16;\n"
        :: "r"(s2u(smem_dst)), "l"(gmem_src));
}
__device__ __forceinline__ void ldm_x4(uint32_t r[4], uint32_t addr) {
    asm volatile("ldmatrix.sync.aligned.m8n8.x4.shared.b16 {%0,%1,%2,%3}, [%4];\n"
        : "=r"(r[0]), "=r"(r[1]), "=r"(r[2]), "=r"(r[3]) : "r"(addr));
}
__device__ __forceinline__ void ldm_x4t(uint32_t r[4], uint32_t addr) {
    asm volatile("ldmatrix.sync.aligned.m8n8.x4.trans.shared.b16 {%0,%1,%2,%3}, [%4];\n"
        : "=r"(r[0]), "=r"(r[1]), "=r"(r[2]), "=r"(r[3]) : "r"(addr));
}
__device__ __forceinline__ void mma_bf16(float c[4], const uint32_t a[4], const uint32_t b[2]) {
    asm volatile("mma.sync.aligned.m16n8k16.row.col.f32.bf16.bf16.f32 "
        "{%0,%1,%2,%3}, {%4,%5,%6,%7}, {%8,%9}, {%0,%1,%2,%3};\n"
        : "+f"(c[0]), "+f"(c[1]), "+f"(c[2]), "+f"(c[3])
        : "r"(a[0]), "r"(a[1]), "r"(a[2]), "r"(a[3]), "r"(b[0]), "r"(b[1]));
}
__device__ __forceinline__ void mma_f16(float c[4], const uint32_t a[4], const uint32_t b[2]) {
    asm volatile("mma.sync.aligned.m16n8k16.row.col.f32.f16.f16.f32 "
        "{%0,%1,%2,%3}, {%4,%5,%6,%7}, {%8,%9}, {%0,%1,%2,%3};\n"
        : "+f"(c[0]), "+f"(c[1]), "+f"(c[2]), "+f"(c[3])
        : "r"(a[0]), "r"(a[1]), "r"(a[2]), "r"(a[3]), "r"(b[0]), "r"(b[1]));
}
__device__ __forceinline__ uint16_t pack_e4m3x2(float lo, float hi) {
    uint16_t r;
    asm("cvt.rn.satfinite.e4m3x2.f32 %0, %1, %2;" : "=h"(r) : "f"(hi), "f"(lo));
    return r;
}
__device__ __forceinline__ __half2 e4m3x2_to_h2(uint32_t u) {
    uint32_t r;
    asm("cvt.rn.f16x2.e4m3x2 %0, %1;" : "=r"(r) : "h"((uint16_t)u));
    return *(__half2*)&r;
}

// smem layout constants for proj
#define ASTR 136
#define BSTR 264
#define BS_ELEMS  (128 * BSTR)
#define AST_ELEMS (32 * ASTR)
#define PROJ_SMEM ((BS_ELEMS + 2 * AST_ELEMS) * 2)   // 84992 bytes

// ---------------------------------------------------------------------------
// Kernel 0: one-time weight conversion. Wp fp32->bf16 (8192 f4), W1 fp32->fp16
// (4096 f4). 48 blocks x 256.
// ---------------------------------------------------------------------------
__global__ __launch_bounds__(256) void wt_convert(const float* __restrict__ Wp,
                                                  const float* __restrict__ W1)
{
    int i = blockIdx.x * 256 + threadIdx.x;
    if (i < 8192) {
        float4 v = *(const float4*)&Wp[i * 4];
        __nv_bfloat162* dst = (__nv_bfloat162*)&g_wp[i * 4];
        dst[0] = __floats2bfloat162_rn(v.x, v.y);
        dst[1] = __floats2bfloat162_rn(v.z, v.w);
    } else {
        int j = i - 8192;   // < 4096
        float4 v = *(const float4*)&W1[j * 4];
        __half2* dst = (__half2*)&g_w1h[j * 4];
        dst[0] = __floats2half2_rn(v.x, v.y);
        dst[1] = __floats2half2_rn(v.z, v.w);
    }
}

// ---------------------------------------------------------------------------
// Kernel 1: projection GEMM -> fp8 vm.  Wp via cp.async from g_wp.
// ---------------------------------------------------------------------------
__global__ __launch_bounds__(256) void proj_kernel(const float* __restrict__ fmap)
{
    extern __shared__ __align__(16) __nv_bfloat16 sm[];
    __nv_bfloat16* Bs  = sm;               // [128 n][BSTR k]
    __nv_bfloat16* AsT = sm + BS_ELEMS;    // [2 buf][32 k][ASTR m]

    const int b      = blockIdx.y;
    const int m_base = blockIdx.x * 128;
    const int tid    = threadIdx.x;
    const int lane   = tid & 31, warp = tid >> 5;

    // async-load whole Wp bf16 into padded smem rows (2 threads per row)
    {
        const int row = tid >> 1;
        const int c0  = (tid & 1) * 16;
#pragma unroll
        for (int c = 0; c < 16; c++) {
            int chunk = c0 + c;
            cp_async16(&Bs[row * BSTR + chunk * 8], &g_wp[row * C_ + chunk * 8]);
        }
        asm volatile("cp.async.commit_group;\n" ::: "memory");
    }

    const int lk = tid >> 3;
    const int l8 = tid & 7;
    const float* fbase = fmap + (size_t)b * C_ * HW_ + m_base;

    float4 st[4];
#pragma unroll
    for (int j = 0; j < 4; j++)
        st[j] = *(const float4*)&fbase[(size_t)lk * HW_ + (l8 + 8 * j) * 4];
    {
        __nv_bfloat16* A0 = AsT;
#pragma unroll
        for (int j = 0; j < 4; j++) {
            int m = (l8 + 8 * j) * 4;
            __nv_bfloat162* d2 = (__nv_bfloat162*)&A0[lk * ASTR + m];
            d2[0] = __floats2bfloat162_rn(st[j].x, st[j].y);
            d2[1] = __floats2bfloat162_rn(st[j].z, st[j].w);
        }
    }
    asm volatile("cp.async.wait_group 0;\n" ::: "memory");
    __syncthreads();

    const int wm = (warp & 3) * 32;
    const int wn = (warp >> 2) * 64;

    float acc[2][8][4];
#pragma unroll
    for (int mt = 0; mt < 2; mt++)
#pragma unroll
        for (int nt = 0; nt < 8; nt++)
#pragma unroll
            for (int q = 0; q < 4; q++) acc[mt][nt][q] = 0.f;

    const uint32_t bbase = s2u(Bs);

    for (int kc = 0; kc < 8; kc++) {
        if (kc < 7) {
#pragma unroll
            for (int j = 0; j < 4; j++)
                st[j] = *(const float4*)&fbase[(size_t)((kc + 1) * 32 + lk) * HW_ + (l8 + 8 * j) * 4];
        }
        const uint32_t abase = s2u(AsT + (kc & 1) * AST_ELEMS);

#pragma unroll
        for (int ks = 0; ks < 2; ks++) {
            uint32_t af[2][4];
#pragma unroll
            for (int mt = 0; mt < 2; mt++) {
                int row = ks * 16 + (lane & 7) + ((lane >> 4) << 3);
                int col = wm + mt * 16 + ((lane >> 3) & 1) * 8;
                ldm_x4t(af[mt], abase + (row * ASTR + col) * 2);
            }
            uint32_t bf[8][2];
#pragma unroll
            for (int np = 0; np < 4; np++) {
                int n = wn + np * 16 + (lane & 7) + ((lane >> 4) << 3);
                int k = kc * 32 + ks * 16 + ((lane >> 3) & 1) * 8;
                uint32_t r[4];
                ldm_x4(r, bbase + (n * BSTR + k) * 2);
                bf[2 * np][0]     = r[0];  bf[2 * np][1]     = r[1];
                bf[2 * np + 1][0] = r[2];  bf[2 * np + 1][1] = r[3];
            }
#pragma unroll
            for (int mt = 0; mt < 2; mt++)
#pragma unroll
                for (int nt = 0; nt < 8; nt++)
                    mma_bf16(acc[mt][nt], af[mt], bf[nt]);
        }

        if (kc < 7) {
            __nv_bfloat16* An = AsT + ((kc + 1) & 1) * AST_ELEMS;
#pragma unroll
            for (int j = 0; j < 4; j++) {
                int m = (l8 + 8 * j) * 4;
                __nv_bfloat162* d2 = (__nv_bfloat162*)&An[lk * ASTR + m];
                d2[0] = __floats2bfloat162_rn(st[j].x, st[j].y);
                d2[1] = __floats2bfloat162_rn(st[j].z, st[j].w);
            }
        }
        __syncthreads();
    }

    uint8_t* out = g_vm8 + ((size_t)b * HW_ + m_base) * D_;
#pragma unroll
    for (int mt = 0; mt < 2; mt++) {
#pragma unroll
        for (int nt = 0; nt < 8; nt++) {
            int r0 = wm + mt * 16 + (lane >> 2);
            int d0 = wn + nt * 8 + (lane & 3) * 2;
            *(uint16_t*)&out[(size_t)r0 * D_ + d0] =
                pack_e4m3x2(acc[mt][nt][0], acc[mt][nt][1]);
            *(uint16_t*)&out[(size_t)(r0 + 8) * D_ + d0] =
                pack_e4m3x2(acc[mt][nt][2], acc[mt][nt][3]);
        }
    }
}

// ---------------------------------------------------------------------------
// Kernel 2: branch-free 4x4 stencil sampler (R4 shape: warp/point, LDG.32).
// ---------------------------------------------------------------------------
__global__ __launch_bounds__(256, 4) void sample_kernel(const float* __restrict__ coords)
{
    const int tid  = threadIdx.x;
    const int lane = tid & 31, warp = tid >> 5;
    const int ptBase = blockIdx.x * 64 + warp * 8;
    const float inv9 = 1.f / 9.f;

#pragma unroll 1
    for (int i = 0; i < 8; i++) {
        int gpt = ptBase + i;
        int b   = gpt >> 14;

        float cx = coords[2 * gpt], cy = coords[2 * gpt + 1];
        float ix = cx * 127.f, iy = cy * 127.f;
        float xf = floorf(ix), yf = floorf(iy);
        int   x0 = (int)xf,    y0 = (int)yf;
        float fx = ix - xf,    fy = iy - yf;
        float Xw[4] = {1.f - fx, 1.f, 1.f, fx};
        float Yw[4] = {1.f - fy, 1.f, 1.f, fy};

        float wx[4], wy[4];
        int   px[4], py[4];
#pragma unroll
        for (int q = 0; q < 4; q++) {
            int x = x0 - 1 + q;
            bool vx = ((unsigned)x < 128u);
            wx[q] = vx ? Xw[q] : 0.f;
            px[q] = vx ? x : 0;
            int y = y0 - 1 + q;
            bool vy = ((unsigned)y < 128u);
            wy[q] = vy ? (Yw[q] * inv9) : 0.f;
            py[q] = vy ? y : 0;
        }

        const uint32_t* vmb = ((const uint32_t*)g_vm8) + (size_t)b * HW_ * 32 + lane;
        uint32_t off[16];
#pragma unroll
        for (int j = 0; j < 4; j++)
#pragma unroll
            for (int q = 0; q < 4; q++)
                off[j * 4 + q] = (uint32_t)(py[j] * W_ + px[q]) * 32u;

        uint32_t v[16];
#pragma unroll
        for (int t = 0; t < 16; t++) v[t] = vmb[off[t]];

        __half2 a01 = __half2(__float2half(0.f), __float2half(0.f));
        __half2 a23 = a01;
#pragma unroll
        for (int j = 0; j < 4; j++)
#pragma unroll
            for (int q = 0; q < 4; q++) {
                int t = j * 4 + q;
                __half2 w2 = __float2half2_rn(wy[j] * wx[q]);
                a01 = __hfma2(e4m3x2_to_h2(v[t] & 0xffffu), w2, a01);
                a23 = __hfma2(e4m3x2_to_h2(v[t] >> 16), w2, a23);
            }

        uint2 pk;
        pk.x = *(uint32_t*)&a01;
        pk.y = *(uint32_t*)&a23;
        *(uint2*)&g_feat[(size_t)gpt * D_ + lane * 4] = pk;
    }
}

// ---------------------------------------------------------------------------
// Kernel 3: MLP GEMM (fp16 mma). Prologue fully via cp.async (feat + W1h).
// ---------------------------------------------------------------------------
#define FSTR 136
#define FEAT_ELEMS (128 * FSTR)
#define MLP_SMEM (2 * FEAT_ELEMS * 2)   // 69632 bytes

__global__ __launch_bounds__(256) void mlp_kernel(
    const float* __restrict__ coords, const float* __restrict__ b1,
    const float* __restrict__ W2,     const float* __restrict__ b2,
    float* __restrict__ out)
{
    extern __shared__ __align__(16) __half smh[];
    __half* Af  = smh;                 // [128 pt][FSTR]
    __half* W1h = smh + FEAT_ELEMS;    // [128 j][FSTR]
    float*  red = (float*)smh;         // aliases Af after GEMM

    const int tid  = threadIdx.x;
    const int lane = tid & 31, warp = tid >> 5;
    const int ptBase = blockIdx.x * 128;

    // async prologue: feat tile (2048 x 16B) + W1h (2048 x 16B)
    {
        const __half* fsrc = g_feat + (size_t)ptBase * D_;
#pragma unroll
        for (int i = 0; i < 8; i++) {
            int idx = i * 256 + tid;
            int row = idx >> 4, c8 = (idx & 15) * 8;
            cp_async16(&Af[row * FSTR + c8], fsrc + idx * 8);
        }
#pragma unroll
        for (int i = 0; i < 8; i++) {
            int idx = i * 256 + tid;
            int row = idx >> 4, c8 = (idx & 15) * 8;
            cp_async16(&W1h[row * FSTR + c8], g_w1h + idx * 8);
        }
        asm volatile("cp.async.commit_group;\n" ::: "memory");
    }

    // load epilogue constants while DMA in flight
    const int wm = (warp & 3) * 32;
    const int wn = (warp >> 2) * 64;
    float2 b1v[8], w20v[8], w21v[8];
#pragma unroll
    for (int nt = 0; nt < 8; nt++) {
        int j = wn + nt * 8 + (lane & 3) * 2;
        b1v[nt]  = *(const float2*)&b1[j];
        w20v[nt] = *(const float2*)&W2[j];
        w21v[nt] = *(const float2*)&W2[128 + j];
    }

    asm volatile("cp.async.wait_group 0;\n" ::: "memory");
    __syncthreads();

    float acc[2][8][4];
#pragma unroll
    for (int mt = 0; mt < 2; mt++)
#pragma unroll
        for (int nt = 0; nt < 8; nt++)
#pragma unroll
            for (int q = 0; q < 4; q++) acc[mt][nt][q] = 0.f;

    const uint32_t abase = s2u(Af);
    const uint32_t bbase = s2u(W1h);

#pragma unroll
    for (int kc = 0; kc < 8; kc++) {
        int k0 = kc * 16;
        uint32_t af[2][4];
#pragma unroll
        for (int mt = 0; mt < 2; mt++) {
            int row = wm + mt * 16 + (lane & 15);
            int col = k0 + ((lane >> 4) << 3);
            ldm_x4(af[mt], abase + (row * FSTR + col) * 2);
        }
        uint32_t bf[8][2];
#pragma unroll
        for (int np = 0; np < 4; np++) {
            int n = wn + np * 16 + (lane & 7) + ((lane >> 4) << 3);
            int k = k0 + ((lane >> 3) & 1) * 8;
            uint32_t r[4];
            ldm_x4(r, bbase + (n * FSTR + k) * 2);
            bf[2 * np][0]     = r[0];  bf[2 * np][1]     = r[1];
            bf[2 * np + 1][0] = r[2];  bf[2 * np + 1][1] = r[3];
        }
#pragma unroll
        for (int mt = 0; mt < 2; mt++)
#pragma unroll
            for (int nt = 0; nt < 8; nt++)
                mma_f16(acc[mt][nt], af[mt], bf[nt]);
    }

    float s0[2][2], s1[2][2];
#pragma unroll
    for (int mt = 0; mt < 2; mt++)
#pragma unroll
        for (int hh = 0; hh < 2; hh++) { s0[mt][hh] = 0.f; s1[mt][hh] = 0.f; }
#pragma unroll
    for (int mt = 0; mt < 2; mt++)
#pragma unroll
        for (int nt = 0; nt < 8; nt++) {
            float h00 = fmaxf(acc[mt][nt][0] + b1v[nt].x, 0.f);
            float h01 = fmaxf(acc[mt][nt][1] + b1v[nt].y, 0.f);
            float h10 = fmaxf(acc[mt][nt][2] + b1v[nt].x, 0.f);
            float h11 = fmaxf(acc[mt][nt][3] + b1v[nt].y, 0.f);
            s0[mt][0] = fmaf(w20v[nt].x, h00, s0[mt][0]);
            s0[mt][0] = fmaf(w20v[nt].y, h01, s0[mt][0]);
            s1[mt][0] = fmaf(w21v[nt].x, h00, s1[mt][0]);
            s1[mt][0] = fmaf(w21v[nt].y, h01, s1[mt][0]);
            s0[mt][1] = fmaf(w20v[nt].x, h10, s0[mt][1]);
            s0[mt][1] = fmaf(w20v[nt].y, h11, s0[mt][1]);
            s1[mt][1] = fmaf(w21v[nt].x, h10, s1[mt][1]);
            s1[mt][1] = fmaf(w21v[nt].y, h11, s1[mt][1]);
        }

    __syncthreads();

    int p = (warp >> 2) * 4 + (lane & 3);
#pragma unroll
    for (int mt = 0; mt < 2; mt++)
#pragma unroll
        for (int hh = 0; hh < 2; hh++) {
            int row = wm + mt * 16 + (lane >> 2) + 8 * hh;
            red[(p * 128 + row) * 2 + 0] = s0[mt][hh];
            red[(p * 128 + row) * 2 + 1] = s1[mt][hh];
        }
    __syncthreads();

    {
        int pt = tid >> 1, c = tid & 1;
        float s = b2[c];
#pragma unroll
        for (int g = 0; g < 8; g++) s += red[(g * 128 + pt) * 2 + c];
        float v = tanhf(s) * MAX_DELTA;
        int gi = (ptBase + pt) * 2 + c;
        out[gi] = coords[gi] + v;
    }
}

// ---------------------------------------------------------------------------
extern "C" void kernel_launch(void* const* d_in, const int* in_sizes, int n_in,
                              void* d_out, int out_size)
{
    (void)in_sizes; (void)n_in; (void)out_size;
    const float* fmap   = (const float*)d_in[0];
    const float* coords = (const float*)d_in[1];
    const float* Wp     = (const float*)d_in[2];
    const float* W1     = (const float*)d_in[3];
    const float* b1     = (const float*)d_in[4];
    const float* W2     = (const float*)d_in[5];
    const float* b2     = (const float*)d_in[6];
    float* out = (float*)d_out;

    wt_convert<<<48, 256>>>(Wp, W1);

    cudaFuncSetAttribute(proj_kernel,
                         cudaFuncAttributeMaxDynamicSharedMemorySize, PROJ_SMEM);
    proj_kernel<<<dim3(HW_ / 128, B_), 256, PROJ_SMEM>>>(fmap);

    sample_kernel<<<(B_ * T_) / 64, 256>>>(coords);

    cudaFuncSetAttribute(mlp_kernel,
                         cudaFuncAttributeMaxDynamicSharedMemorySize, MLP_SMEM);
    mlp_kernel<<<(B_ * T_) / 128, 256, MLP_SMEM>>>(coords, b1, W2, b2, out);
}

// round 7
// speedup vs baseline: 1.0343x; 1.0343x over previous
#include <cuda_runtime.h>
#include <cuda_bf16.h>
#include <cuda_fp16.h>
#include <math.h>
#include <stdint.h>

#define B_   4
#define C_   256
#define D_   128
#define HW_  16384
#define W_   128
#define T_   16384
#define MAX_DELTA 0.0009765625f   // 0.5/512

__device__ uint8_t g_vm8[(size_t)B_ * HW_ * D_];       // fp8 vm [b][pix][d]
__device__ __half g_feat[(size_t)B_ * T_ * D_];        // fp16 feat [pt][d]
__device__ __nv_bfloat16 g_wp[D_ * C_];                // bf16 Wp [d][c]
__device__ __half g_w1h[D_ * D_];                      // fp16 W1 [j][k]

// ---------------------------------------------------------------------------
__device__ __forceinline__ uint32_t s2u(const void* p) {
    return (uint32_t)__cvta_generic_to_shared(p);
}
__device__ __forceinline__ void cp_async16(void* smem_dst, const void* gmem_src) {
    asm volatile("cp.async.cg.shared.global [%0], [%1], 16;\n"
        :: "r"(s2u(smem_dst)), "l"(gmem_src));
}
__device__ __forceinline__ void ldm_x4(uint32_t r[4], uint32_t addr) {
    asm volatile("ldmatrix.sync.aligned.m8n8.x4.shared.b16 {%0,%1,%2,%3}, [%4];\n"
        : "=r"(r[0]), "=r"(r[1]), "=r"(r[2]), "=r"(r[3]) : "r"(addr));
}
__device__ __forceinline__ void ldm_x4t(uint32_t r[4], uint32_t addr) {
    asm volatile("ldmatrix.sync.aligned.m8n8.x4.trans.shared.b16 {%0,%1,%2,%3}, [%4];\n"
        : "=r"(r[0]), "=r"(r[1]), "=r"(r[2]), "=r"(r[3]) : "r"(addr));
}
__device__ __forceinline__ void mma_bf16(float c[4], const uint32_t a[4], const uint32_t b[2]) {
    asm volatile("mma.sync.aligned.m16n8k16.row.col.f32.bf16.bf16.f32 "
        "{%0,%1,%2,%3}, {%4,%5,%6,%7}, {%8,%9}, {%0,%1,%2,%3};\n"
        : "+f"(c[0]), "+f"(c[1]), "+f"(c[2]), "+f"(c[3])
        : "r"(a[0]), "r"(a[1]), "r"(a[2]), "r"(a[3]), "r"(b[0]), "r"(b[1]));
}
__device__ __forceinline__ void mma_f16(float c[4], const uint32_t a[4], const uint32_t b[2]) {
    asm volatile("mma.sync.aligned.m16n8k16.row.col.f32.f16.f16.f32 "
        "{%0,%1,%2,%3}, {%4,%5,%6,%7}, {%8,%9}, {%0,%1,%2,%3};\n"
        : "+f"(c[0]), "+f"(c[1]), "+f"(c[2]), "+f"(c[3])
        : "r"(a[0]), "r"(a[1]), "r"(a[2]), "r"(a[3]), "r"(b[0]), "r"(b[1]));
}
__device__ __forceinline__ uint16_t pack_e4m3x2(float lo, float hi) {
    uint16_t r;
    asm("cvt.rn.satfinite.e4m3x2.f32 %0, %1, %2;" : "=h"(r) : "f"(hi), "f"(lo));
    return r;
}
__device__ __forceinline__ __half2 e4m3x2_to_h2(uint32_t u) {
    uint32_t r;
    asm("cvt.rn.f16x2.e4m3x2 %0, %1;" : "=r"(r) : "h"((uint16_t)u));
    return *(__half2*)&r;
}

// smem layout constants for proj
#define ASTR 136
#define BSTR 264
#define BS_ELEMS  (128 * BSTR)
#define AST_ELEMS (32 * ASTR)
#define PROJ_SMEM ((BS_ELEMS + 2 * AST_ELEMS) * 2)   // 84992 bytes

// ---------------------------------------------------------------------------
// Kernel 0: one-time weight conversion.
// ---------------------------------------------------------------------------
__global__ __launch_bounds__(256) void wt_convert(const float* __restrict__ Wp,
                                                  const float* __restrict__ W1)
{
    int i = blockIdx.x * 256 + threadIdx.x;
    if (i < 8192) {
        float4 v = *(const float4*)&Wp[i * 4];
        __nv_bfloat162* dst = (__nv_bfloat162*)&g_wp[i * 4];
        dst[0] = __floats2bfloat162_rn(v.x, v.y);
        dst[1] = __floats2bfloat162_rn(v.z, v.w);
    } else {
        int j = i - 8192;
        float4 v = *(const float4*)&W1[j * 4];
        __half2* dst = (__half2*)&g_w1h[j * 4];
        dst[0] = __floats2half2_rn(v.x, v.y);
        dst[1] = __floats2half2_rn(v.z, v.w);
    }
}

// ---------------------------------------------------------------------------
// Kernel 1: projection GEMM -> fp8 vm (cp.async Wp prologue).
// ---------------------------------------------------------------------------
__global__ __launch_bounds__(256) void proj_kernel(const float* __restrict__ fmap)
{
    extern __shared__ __align__(16) __nv_bfloat16 sm[];
    __nv_bfloat16* Bs  = sm;
    __nv_bfloat16* AsT = sm + BS_ELEMS;

    const int b      = blockIdx.y;
    const int m_base = blockIdx.x * 128;
    const int tid    = threadIdx.x;
    const int lane   = tid & 31, warp = tid >> 5;

    {
        const int row = tid >> 1;
        const int c0  = (tid & 1) * 16;
#pragma unroll
        for (int c = 0; c < 16; c++) {
            int chunk = c0 + c;
            cp_async16(&Bs[row * BSTR + chunk * 8], &g_wp[row * C_ + chunk * 8]);
        }
        asm volatile("cp.async.commit_group;\n" ::: "memory");
    }

    const int lk = tid >> 3;
    const int l8 = tid & 7;
    const float* fbase = fmap + (size_t)b * C_ * HW_ + m_base;

    float4 st[4];
#pragma unroll
    for (int j = 0; j < 4; j++)
        st[j] = *(const float4*)&fbase[(size_t)lk * HW_ + (l8 + 8 * j) * 4];
    {
        __nv_bfloat16* A0 = AsT;
#pragma unroll
        for (int j = 0; j < 4; j++) {
            int m = (l8 + 8 * j) * 4;
            __nv_bfloat162* d2 = (__nv_bfloat162*)&A0[lk * ASTR + m];
            d2[0] = __floats2bfloat162_rn(st[j].x, st[j].y);
            d2[1] = __floats2bfloat162_rn(st[j].z, st[j].w);
        }
    }
    asm volatile("cp.async.wait_group 0;\n" ::: "memory");
    __syncthreads();

    const int wm = (warp & 3) * 32;
    const int wn = (warp >> 2) * 64;

    float acc[2][8][4];
#pragma unroll
    for (int mt = 0; mt < 2; mt++)
#pragma unroll
        for (int nt = 0; nt < 8; nt++)
#pragma unroll
            for (int q = 0; q < 4; q++) acc[mt][nt][q] = 0.f;

    const uint32_t bbase = s2u(Bs);

    for (int kc = 0; kc < 8; kc++) {
        if (kc < 7) {
#pragma unroll
            for (int j = 0; j < 4; j++)
                st[j] = *(const float4*)&fbase[(size_t)((kc + 1) * 32 + lk) * HW_ + (l8 + 8 * j) * 4];
        }
        const uint32_t abase = s2u(AsT + (kc & 1) * AST_ELEMS);

#pragma unroll
        for (int ks = 0; ks < 2; ks++) {
            uint32_t af[2][4];
#pragma unroll
            for (int mt = 0; mt < 2; mt++) {
                int row = ks * 16 + (lane & 7) + ((lane >> 4) << 3);
                int col = wm + mt * 16 + ((lane >> 3) & 1) * 8;
                ldm_x4t(af[mt], abase + (row * ASTR + col) * 2);
            }
            uint32_t bf[8][2];
#pragma unroll
            for (int np = 0; np < 4; np++) {
                int n = wn + np * 16 + (lane & 7) + ((lane >> 4) << 3);
                int k = kc * 32 + ks * 16 + ((lane >> 3) & 1) * 8;
                uint32_t r[4];
                ldm_x4(r, bbase + (n * BSTR + k) * 2);
                bf[2 * np][0]     = r[0];  bf[2 * np][1]     = r[1];
                bf[2 * np + 1][0] = r[2];  bf[2 * np + 1][1] = r[3];
            }
#pragma unroll
            for (int mt = 0; mt < 2; mt++)
#pragma unroll
                for (int nt = 0; nt < 8; nt++)
                    mma_bf16(acc[mt][nt], af[mt], bf[nt]);
        }

        if (kc < 7) {
            __nv_bfloat16* An = AsT + ((kc + 1) & 1) * AST_ELEMS;
#pragma unroll
            for (int j = 0; j < 4; j++) {
                int m = (l8 + 8 * j) * 4;
                __nv_bfloat162* d2 = (__nv_bfloat162*)&An[lk * ASTR + m];
                d2[0] = __floats2bfloat162_rn(st[j].x, st[j].y);
                d2[1] = __floats2bfloat162_rn(st[j].z, st[j].w);
            }
        }
        __syncthreads();
    }

    uint8_t* out = g_vm8 + ((size_t)b * HW_ + m_base) * D_;
#pragma unroll
    for (int mt = 0; mt < 2; mt++) {
#pragma unroll
        for (int nt = 0; nt < 8; nt++) {
            int r0 = wm + mt * 16 + (lane >> 2);
            int d0 = wn + nt * 8 + (lane & 3) * 2;
            *(uint16_t*)&out[(size_t)r0 * D_ + d0] =
                pack_e4m3x2(acc[mt][nt][0], acc[mt][nt][1]);
            *(uint16_t*)&out[(size_t)(r0 + 8) * D_ + d0] =
                pack_e4m3x2(acc[mt][nt][2], acc[mt][nt][3]);
        }
    }
}

// ---------------------------------------------------------------------------
// Kernel 2: branch-free 4x4 stencil sampler (R4 shape: warp/point, LDG.32).
// ---------------------------------------------------------------------------
__global__ __launch_bounds__(256, 4) void sample_kernel(const float* __restrict__ coords)
{
    const int tid  = threadIdx.x;
    const int lane = tid & 31, warp = tid >> 5;
    const int ptBase = blockIdx.x * 64 + warp * 8;
    const float inv9 = 1.f / 9.f;

#pragma unroll 1
    for (int i = 0; i < 8; i++) {
        int gpt = ptBase + i;
        int b   = gpt >> 14;

        float cx = coords[2 * gpt], cy = coords[2 * gpt + 1];
        float ix = cx * 127.f, iy = cy * 127.f;
        float xf = floorf(ix), yf = floorf(iy);
        int   x0 = (int)xf,    y0 = (int)yf;
        float fx = ix - xf,    fy = iy - yf;
        float Xw[4] = {1.f - fx, 1.f, 1.f, fx};
        float Yw[4] = {1.f - fy, 1.f, 1.f, fy};

        float wx[4], wy[4];
        int   px[4], py[4];
#pragma unroll
        for (int q = 0; q < 4; q++) {
            int x = x0 - 1 + q;
            bool vx = ((unsigned)x < 128u);
            wx[q] = vx ? Xw[q] : 0.f;
            px[q] = vx ? x : 0;
            int y = y0 - 1 + q;
            bool vy = ((unsigned)y < 128u);
            wy[q] = vy ? (Yw[q] * inv9) : 0.f;
            py[q] = vy ? y : 0;
        }

        const uint32_t* vmb = ((const uint32_t*)g_vm8) + (size_t)b * HW_ * 32 + lane;
        uint32_t off[16];
#pragma unroll
        for (int j = 0; j < 4; j++)
#pragma unroll
            for (int q = 0; q < 4; q++)
                off[j * 4 + q] = (uint32_t)(py[j] * W_ + px[q]) * 32u;

        uint32_t v[16];
#pragma unroll
        for (int t = 0; t < 16; t++) v[t] = vmb[off[t]];

        __half2 a01 = __half2(__float2half(0.f), __float2half(0.f));
        __half2 a23 = a01;
#pragma unroll
        for (int j = 0; j < 4; j++)
#pragma unroll
            for (int q = 0; q < 4; q++) {
                int t = j * 4 + q;
                __half2 w2 = __float2half2_rn(wy[j] * wx[q]);
                a01 = __hfma2(e4m3x2_to_h2(v[t] & 0xffffu), w2, a01);
                a23 = __hfma2(e4m3x2_to_h2(v[t] >> 16), w2, a23);
            }

        uint2 pk;
        pk.x = *(uint32_t*)&a01;
        pk.y = *(uint32_t*)&a23;
        *(uint2*)&g_feat[(size_t)gpt * D_ + lane * 4] = pk;
    }
}

// ---------------------------------------------------------------------------
// Kernel 3: MLP GEMM, persistent over 2 tiles per block.
// smem: W1h [128][FSTR] + Af[2][128][FSTR] + red[2][128][2] floats.
// W1 loaded once; feat double-buffered via cp.async; shuffle-reduce epilogue.
// ---------------------------------------------------------------------------
#define FSTR 136
#define TILE_ELEMS (128 * FSTR)
#define MLP_SMEM ((3 * TILE_ELEMS) * 2 + 2 * 128 * 2 * 4)   // 106496 B

__global__ __launch_bounds__(256) void mlp_kernel(
    const float* __restrict__ coords, const float* __restrict__ b1,
    const float* __restrict__ W2,     const float* __restrict__ b2,
    float* __restrict__ out)
{
    extern __shared__ __align__(16) __half smh[];
    __half* W1h = smh;                             // [128][FSTR]
    __half* Af0 = smh + TILE_ELEMS;                // buffer 0
    __half* Af1 = smh + 2 * TILE_ELEMS;            // buffer 1
    float*  red = (float*)(smh + 3 * TILE_ELEMS);  // [2][128][2]

    const int tid  = threadIdx.x;
    const int lane = tid & 31, warp = tid >> 5;
    const int wm = (warp & 3) * 32;
    const int wn = (warp >> 2) * 64;

    // prologue: W1 + feat tile0 (group A), feat tile1 (group B)
    {
#pragma unroll
        for (int i = 0; i < 8; i++) {
            int idx = i * 256 + tid;
            int row = idx >> 4, c8 = (idx & 15) * 8;
            cp_async16(&W1h[row * FSTR + c8], g_w1h + idx * 8);
        }
        const __half* f0 = g_feat + (size_t)(blockIdx.x * 2) * 128 * D_;
#pragma unroll
        for (int i = 0; i < 8; i++) {
            int idx = i * 256 + tid;
            int row = idx >> 4, c8 = (idx & 15) * 8;
            cp_async16(&Af0[row * FSTR + c8], f0 + idx * 8);
        }
        asm volatile("cp.async.commit_group;\n" ::: "memory");
        const __half* f1 = f0 + 128 * D_;
#pragma unroll
        for (int i = 0; i < 8; i++) {
            int idx = i * 256 + tid;
            int row = idx >> 4, c8 = (idx & 15) * 8;
            cp_async16(&Af1[row * FSTR + c8], f1 + idx * 8);
        }
        asm volatile("cp.async.commit_group;\n" ::: "memory");
    }

#pragma unroll 1
    for (int t = 0; t < 2; t++) {
        if (t == 0)
            asm volatile("cp.async.wait_group 1;\n" ::: "memory");
        else
            asm volatile("cp.async.wait_group 0;\n" ::: "memory");
        __syncthreads();

        const int ptBase = (blockIdx.x * 2 + t) * 128;
        const __half* Af = t ? Af1 : Af0;

        float acc[2][8][4];
#pragma unroll
        for (int mt = 0; mt < 2; mt++)
#pragma unroll
            for (int nt = 0; nt < 8; nt++)
#pragma unroll
                for (int q = 0; q < 4; q++) acc[mt][nt][q] = 0.f;

        const uint32_t abase = s2u(Af);
        const uint32_t bbase = s2u(W1h);

#pragma unroll
        for (int kc = 0; kc < 8; kc++) {
            int k0 = kc * 16;
            uint32_t af[2][4];
#pragma unroll
            for (int mt = 0; mt < 2; mt++) {
                int row = wm + mt * 16 + (lane & 15);
                int col = k0 + ((lane >> 4) << 3);
                ldm_x4(af[mt], abase + (row * FSTR + col) * 2);
            }
            uint32_t bf[8][2];
#pragma unroll
            for (int np = 0; np < 4; np++) {
                int n = wn + np * 16 + (lane & 7) + ((lane >> 4) << 3);
                int k = k0 + ((lane >> 3) & 1) * 8;
                uint32_t r[4];
                ldm_x4(r, bbase + (n * FSTR + k) * 2);
                bf[2 * np][0]     = r[0];  bf[2 * np][1]     = r[1];
                bf[2 * np + 1][0] = r[2];  bf[2 * np + 1][1] = r[3];
            }
#pragma unroll
            for (int mt = 0; mt < 2; mt++)
#pragma unroll
                for (int nt = 0; nt < 8; nt++)
                    mma_f16(acc[mt][nt], af[mt], bf[nt]);
        }

        // epilogue: relu(acc+b1), partial W2 @ h, shuffle-reduce over lane&3
        float2 b1v[8], w20v[8], w21v[8];
#pragma unroll
        for (int nt = 0; nt < 8; nt++) {
            int j = wn + nt * 8 + (lane & 3) * 2;
            b1v[nt]  = *(const float2*)&b1[j];
            w20v[nt] = *(const float2*)&W2[j];
            w21v[nt] = *(const float2*)&W2[128 + j];
        }
        float s0[2][2], s1[2][2];
#pragma unroll
        for (int mt = 0; mt < 2; mt++)
#pragma unroll
            for (int hh = 0; hh < 2; hh++) { s0[mt][hh] = 0.f; s1[mt][hh] = 0.f; }
#pragma unroll
        for (int mt = 0; mt < 2; mt++)
#pragma unroll
            for (int nt = 0; nt < 8; nt++) {
                float h00 = fmaxf(acc[mt][nt][0] + b1v[nt].x, 0.f);
                float h01 = fmaxf(acc[mt][nt][1] + b1v[nt].y, 0.f);
                float h10 = fmaxf(acc[mt][nt][2] + b1v[nt].x, 0.f);
                float h11 = fmaxf(acc[mt][nt][3] + b1v[nt].y, 0.f);
                s0[mt][0] = fmaf(w20v[nt].x, h00, s0[mt][0]);
                s0[mt][0] = fmaf(w20v[nt].y, h01, s0[mt][0]);
                s1[mt][0] = fmaf(w21v[nt].x, h00, s1[mt][0]);
                s1[mt][0] = fmaf(w21v[nt].y, h01, s1[mt][0]);
                s0[mt][1] = fmaf(w20v[nt].x, h10, s0[mt][1]);
                s0[mt][1] = fmaf(w20v[nt].y, h11, s0[mt][1]);
                s1[mt][1] = fmaf(w21v[nt].x, h10, s1[mt][1]);
                s1[mt][1] = fmaf(w21v[nt].y, h11, s1[mt][1]);
            }
        // butterfly over the 4 lanes sharing lane>>2 (bits 0-1)
#pragma unroll
        for (int mt = 0; mt < 2; mt++)
#pragma unroll
            for (int hh = 0; hh < 2; hh++) {
#pragma unroll
                for (int ofs = 1; ofs < 4; ofs <<= 1) {
                    s0[mt][hh] += __shfl_xor_sync(0xffffffffu, s0[mt][hh], ofs);
                    s1[mt][hh] += __shfl_xor_sync(0xffffffffu, s1[mt][hh], ofs);
                }
            }
        if ((lane & 3) == 0) {
            int g = warp >> 2;   // n-group 0/1
#pragma unroll
            for (int mt = 0; mt < 2; mt++)
#pragma unroll
                for (int hh = 0; hh < 2; hh++) {
                    int row = wm + mt * 16 + (lane >> 2) + 8 * hh;
                    red[(g * 128 + row) * 2 + 0] = s0[mt][hh];
                    red[(g * 128 + row) * 2 + 1] = s1[mt][hh];
                }
        }
        __syncthreads();

        {
            int pt = tid >> 1, c = tid & 1;
            float s = b2[c] + red[pt * 2 + c] + red[(128 + pt) * 2 + c];
            float v = tanhf(s) * MAX_DELTA;
            int gi = (ptBase + pt) * 2 + c;
            out[gi] = coords[gi] + v;
        }
        __syncthreads();
    }
}

// ---------------------------------------------------------------------------
extern "C" void kernel_launch(void* const* d_in, const int* in_sizes, int n_in,
                              void* d_out, int out_size)
{
    (void)in_sizes; (void)n_in; (void)out_size;
    const float* fmap   = (const float*)d_in[0];
    const float* coords = (const float*)d_in[1];
    const float* Wp     = (const float*)d_in[2];
    const float* W1     = (const float*)d_in[3];
    const float* b1     = (const float*)d_in[4];
    const float* W2     = (const float*)d_in[5];
    const float* b2     = (const float*)d_in[6];
    float* out = (float*)d_out;

    wt_convert<<<48, 256>>>(Wp, W1);

    cudaFuncSetAttribute(proj_kernel,
                         cudaFuncAttributeMaxDynamicSharedMemorySize, PROJ_SMEM);
    proj_kernel<<<dim3(HW_ / 128, B_), 256, PROJ_SMEM>>>(fmap);

    sample_kernel<<<(B_ * T_) / 64, 256>>>(coords);

    cudaFuncSetAttribute(mlp_kernel,
                         cudaFuncAttributeMaxDynamicSharedMemorySize, MLP_SMEM);
    mlp_kernel<<<(B_ * T_) / 256, 256, MLP_SMEM>>>(coords, b1, W2, b2, out);
}

// round 8
// speedup vs baseline: 1.0969x; 1.0606x over previous
#include <cuda_runtime.h>
#include <cuda_bf16.h>
#include <cuda_fp16.h>
#include <math.h>
#include <stdint.h>

#define B_   4
#define C_   256
#define D_   128
#define HW_  16384
#define W_   128
#define T_   16384
#define MAX_DELTA 0.0009765625f   // 0.5/512

__device__ uint8_t g_vm8[(size_t)B_ * HW_ * D_];       // fp8 vm [b][pix][d]
__device__ __half g_feat[(size_t)B_ * T_ * D_];        // fp16 feat [pt][d]
__device__ __nv_bfloat16 g_wp[D_ * C_];                // bf16 Wp [d][c]
__device__ __half g_w1h[D_ * D_];                      // fp16 W1 [j][k]

// ---------------------------------------------------------------------------
__device__ __forceinline__ uint32_t s2u(const void* p) {
    return (uint32_t)__cvta_generic_to_shared(p);
}
__device__ __forceinline__ void cp_async16(void* smem_dst, const void* gmem_src) {
    asm volatile("cp.async.cg.shared.global [%0], [%1], 16;\n"
        :: "r"(s2u(smem_dst)), "l"(gmem_src));
}
__device__ __forceinline__ void ldm_x4(uint32_t r[4], uint32_t addr) {
    asm volatile("ldmatrix.sync.aligned.m8n8.x4.shared.b16 {%0,%1,%2,%3}, [%4];\n"
        : "=r"(r[0]), "=r"(r[1]), "=r"(r[2]), "=r"(r[3]) : "r"(addr));
}
__device__ __forceinline__ void ldm_x4t(uint32_t r[4], uint32_t addr) {
    asm volatile("ldmatrix.sync.aligned.m8n8.x4.trans.shared.b16 {%0,%1,%2,%3}, [%4];\n"
        : "=r"(r[0]), "=r"(r[1]), "=r"(r[2]), "=r"(r[3]) : "r"(addr));
}
__device__ __forceinline__ void mma_bf16(float c[4], const uint32_t a[4], const uint32_t b[2]) {
    asm volatile("mma.sync.aligned.m16n8k16.row.col.f32.bf16.bf16.f32 "
        "{%0,%1,%2,%3}, {%4,%5,%6,%7}, {%8,%9}, {%0,%1,%2,%3};\n"
        : "+f"(c[0]), "+f"(c[1]), "+f"(c[2]), "+f"(c[3])
        : "r"(a[0]), "r"(a[1]), "r"(a[2]), "r"(a[3]), "r"(b[0]), "r"(b[1]));
}
__device__ __forceinline__ void mma_f16(float c[4], const uint32_t a[4], const uint32_t b[2]) {
    asm volatile("mma.sync.aligned.m16n8k16.row.col.f32.f16.f16.f32 "
        "{%0,%1,%2,%3}, {%4,%5,%6,%7}, {%8,%9}, {%0,%1,%2,%3};\n"
        : "+f"(c[0]), "+f"(c[1]), "+f"(c[2]), "+f"(c[3])
        : "r"(a[0]), "r"(a[1]), "r"(a[2]), "r"(a[3]), "r"(b[0]), "r"(b[1]));
}
__device__ __forceinline__ uint16_t pack_e4m3x2(float lo, float hi) {
    uint16_t r;
    asm("cvt.rn.satfinite.e4m3x2.f32 %0, %1, %2;" : "=h"(r) : "f"(hi), "f"(lo));
    return r;
}
__device__ __forceinline__ __half2 e4m3x2_to_h2(uint32_t u) {
    uint32_t r;
    asm("cvt.rn.f16x2.e4m3x2 %0, %1;" : "=r"(r) : "h"((uint16_t)u));
    return *(__half2*)&r;
}

// smem layout constants for proj
#define ASTR 136
#define BSTR 264
#define BS_ELEMS  (128 * BSTR)
#define AST_ELEMS (32 * ASTR)
#define PROJ_SMEM ((BS_ELEMS + 2 * AST_ELEMS) * 2)   // 84992 bytes

// ---------------------------------------------------------------------------
// Kernel 0: one-time weight conversion.
// ---------------------------------------------------------------------------
__global__ __launch_bounds__(256) void wt_convert(const float* __restrict__ Wp,
                                                  const float* __restrict__ W1)
{
    int i = blockIdx.x * 256 + threadIdx.x;
    if (i < 8192) {
        float4 v = *(const float4*)&Wp[i * 4];
        __nv_bfloat162* dst = (__nv_bfloat162*)&g_wp[i * 4];
        dst[0] = __floats2bfloat162_rn(v.x, v.y);
        dst[1] = __floats2bfloat162_rn(v.z, v.w);
    } else {
        int j = i - 8192;
        float4 v = *(const float4*)&W1[j * 4];
        __half2* dst = (__half2*)&g_w1h[j * 4];
        dst[0] = __floats2half2_rn(v.x, v.y);
        dst[1] = __floats2half2_rn(v.z, v.w);
    }
}

// ---------------------------------------------------------------------------
// Kernel 1: projection GEMM -> fp8 vm. Persistent: 2 m-tiles per block,
// Wp loaded once per block (cp.async), fmap prefetch chain crosses tiles.
// grid = (64, 4) = 256 blocks -> single wave at 2 CTA/SM.
// ---------------------------------------------------------------------------
__global__ __launch_bounds__(256) void proj_kernel(const float* __restrict__ fmap)
{
    extern __shared__ __align__(16) __nv_bfloat16 sm[];
    __nv_bfloat16* Bs  = sm;               // [128 n][BSTR k]
    __nv_bfloat16* AsT = sm + BS_ELEMS;    // [2 buf][32 k][ASTR m]

    const int b      = blockIdx.y;
    const int tid    = threadIdx.x;
    const int lane   = tid & 31, warp = tid >> 5;

    // async-load whole Wp bf16 once per block
    {
        const int row = tid >> 1;
        const int c0  = (tid & 1) * 16;
#pragma unroll
        for (int c = 0; c < 16; c++) {
            int chunk = c0 + c;
            cp_async16(&Bs[row * BSTR + chunk * 8], &g_wp[row * C_ + chunk * 8]);
        }
        asm volatile("cp.async.commit_group;\n" ::: "memory");
    }

    const int lk = tid >> 3;
    const int l8 = tid & 7;
    const float* fb = fmap + (size_t)b * C_ * HW_ + blockIdx.x * 256;

    // prefetch chunk 0 (tile 0, kc 0)
    float4 st[4];
#pragma unroll
    for (int j = 0; j < 4; j++)
        st[j] = *(const float4*)&fb[(size_t)lk * HW_ + (l8 + 8 * j) * 4];
    {
        __nv_bfloat16* A0 = AsT;
#pragma unroll
        for (int j = 0; j < 4; j++) {
            int m = (l8 + 8 * j) * 4;
            __nv_bfloat162* d2 = (__nv_bfloat162*)&A0[lk * ASTR + m];
            d2[0] = __floats2bfloat162_rn(st[j].x, st[j].y);
            d2[1] = __floats2bfloat162_rn(st[j].z, st[j].w);
        }
    }
    asm volatile("cp.async.wait_group 0;\n" ::: "memory");
    __syncthreads();

    const int wm = (warp & 3) * 32;
    const int wn = (warp >> 2) * 64;
    const uint32_t bbase = s2u(Bs);

    float acc[2][8][4];
#pragma unroll
    for (int mt = 0; mt < 2; mt++)
#pragma unroll
        for (int nt = 0; nt < 8; nt++)
#pragma unroll
            for (int q = 0; q < 4; q++) acc[mt][nt][q] = 0.f;

#pragma unroll 1
    for (int t = 0; t < 2; t++) {
#pragma unroll 1
        for (int kc = 0; kc < 8; kc++) {
            const int g = t * 8 + kc;
            if (g < 15) {
                // prefetch chunk g+1 (may belong to next tile)
                const int gn = g + 1;
                const float* src = fb + (size_t)((gn & 7) * 32 + lk) * HW_ + ((gn >> 3) * 128);
#pragma unroll
                for (int j = 0; j < 4; j++)
                    st[j] = *(const float4*)&src[(l8 + 8 * j) * 4];
            }
            const uint32_t abase = s2u(AsT + (g & 1) * AST_ELEMS);

#pragma unroll
            for (int ks = 0; ks < 2; ks++) {
                uint32_t af[2][4];
#pragma unroll
                for (int mt = 0; mt < 2; mt++) {
                    int row = ks * 16 + (lane & 7) + ((lane >> 4) << 3);
                    int col = wm + mt * 16 + ((lane >> 3) & 1) * 8;
                    ldm_x4t(af[mt], abase + (row * ASTR + col) * 2);
                }
                uint32_t bf[8][2];
#pragma unroll
                for (int np = 0; np < 4; np++) {
                    int n = wn + np * 16 + (lane & 7) + ((lane >> 4) << 3);
                    int k = kc * 32 + ks * 16 + ((lane >> 3) & 1) * 8;
                    uint32_t r[4];
                    ldm_x4(r, bbase + (n * BSTR + k) * 2);
                    bf[2 * np][0]     = r[0];  bf[2 * np][1]     = r[1];
                    bf[2 * np + 1][0] = r[2];  bf[2 * np + 1][1] = r[3];
                }
#pragma unroll
                for (int mt = 0; mt < 2; mt++)
#pragma unroll
                    for (int nt = 0; nt < 8; nt++)
                        mma_bf16(acc[mt][nt], af[mt], bf[nt]);
            }

            if (g < 15) {
                __nv_bfloat16* An = AsT + ((g + 1) & 1) * AST_ELEMS;
#pragma unroll
                for (int j = 0; j < 4; j++) {
                    int m = (l8 + 8 * j) * 4;
                    __nv_bfloat162* d2 = (__nv_bfloat162*)&An[lk * ASTR + m];
                    d2[0] = __floats2bfloat162_rn(st[j].x, st[j].y);
                    d2[1] = __floats2bfloat162_rn(st[j].z, st[j].w);
                }
            }
            __syncthreads();
        }

        // epilogue tile t: C frags -> fp8 g_vm8 (register-only, no smem)
        uint8_t* outp = g_vm8 + ((size_t)b * HW_ + blockIdx.x * 256 + t * 128) * D_;
#pragma unroll
        for (int mt = 0; mt < 2; mt++) {
#pragma unroll
            for (int nt = 0; nt < 8; nt++) {
                int r0 = wm + mt * 16 + (lane >> 2);
                int d0 = wn + nt * 8 + (lane & 3) * 2;
                *(uint16_t*)&outp[(size_t)r0 * D_ + d0] =
                    pack_e4m3x2(acc[mt][nt][0], acc[mt][nt][1]);
                *(uint16_t*)&outp[(size_t)(r0 + 8) * D_ + d0] =
                    pack_e4m3x2(acc[mt][nt][2], acc[mt][nt][3]);
                acc[mt][nt][0] = acc[mt][nt][1] = acc[mt][nt][2] = acc[mt][nt][3] = 0.f;
            }
        }
    }
}

// ---------------------------------------------------------------------------
// Kernel 2: branch-free 4x4 stencil sampler (R4 shape: warp/point, LDG.32).
// ---------------------------------------------------------------------------
__global__ __launch_bounds__(256, 4) void sample_kernel(const float* __restrict__ coords)
{
    const int tid  = threadIdx.x;
    const int lane = tid & 31, warp = tid >> 5;
    const int ptBase = blockIdx.x * 64 + warp * 8;
    const float inv9 = 1.f / 9.f;

#pragma unroll 1
    for (int i = 0; i < 8; i++) {
        int gpt = ptBase + i;
        int b   = gpt >> 14;

        float cx = coords[2 * gpt], cy = coords[2 * gpt + 1];
        float ix = cx * 127.f, iy = cy * 127.f;
        float xf = floorf(ix), yf = floorf(iy);
        int   x0 = (int)xf,    y0 = (int)yf;
        float fx = ix - xf,    fy = iy - yf;
        float Xw[4] = {1.f - fx, 1.f, 1.f, fx};
        float Yw[4] = {1.f - fy, 1.f, 1.f, fy};

        float wx[4], wy[4];
        int   px[4], py[4];
#pragma unroll
        for (int q = 0; q < 4; q++) {
            int x = x0 - 1 + q;
            bool vx = ((unsigned)x < 128u);
            wx[q] = vx ? Xw[q] : 0.f;
            px[q] = vx ? x : 0;
            int y = y0 - 1 + q;
            bool vy = ((unsigned)y < 128u);
            wy[q] = vy ? (Yw[q] * inv9) : 0.f;
            py[q] = vy ? y : 0;
        }

        const uint32_t* vmb = ((const uint32_t*)g_vm8) + (size_t)b * HW_ * 32 + lane;
        uint32_t off[16];
#pragma unroll
        for (int j = 0; j < 4; j++)
#pragma unroll
            for (int q = 0; q < 4; q++)
                off[j * 4 + q] = (uint32_t)(py[j] * W_ + px[q]) * 32u;

        uint32_t v[16];
#pragma unroll
        for (int t = 0; t < 16; t++) v[t] = vmb[off[t]];

        __half2 a01 = __half2(__float2half(0.f), __float2half(0.f));
        __half2 a23 = a01;
#pragma unroll
        for (int j = 0; j < 4; j++)
#pragma unroll
            for (int q = 0; q < 4; q++) {
                int t = j * 4 + q;
                __half2 w2 = __float2half2_rn(wy[j] * wx[q]);
                a01 = __hfma2(e4m3x2_to_h2(v[t] & 0xffffu), w2, a01);
                a23 = __hfma2(e4m3x2_to_h2(v[t] >> 16), w2, a23);
            }

        uint2 pk;
        pk.x = *(uint32_t*)&a01;
        pk.y = *(uint32_t*)&a23;
        *(uint2*)&g_feat[(size_t)gpt * D_ + lane * 4] = pk;
    }
}

// ---------------------------------------------------------------------------
// Kernel 3: MLP GEMM, persistent over 4 tiles per block (grid 128 = 1 wave).
// W1 loaded once; feat ping-pong, prefetch depth 2; shuffle-reduce epilogue.
// ---------------------------------------------------------------------------
#define FSTR 136
#define TILE_ELEMS (128 * FSTR)
#define MLP_SMEM ((3 * TILE_ELEMS) * 2 + 2 * 128 * 2 * 4)   // 106496 B
#define NTILES 4

__global__ __launch_bounds__(256) void mlp_kernel(
    const float* __restrict__ coords, const float* __restrict__ b1,
    const float* __restrict__ W2,     const float* __restrict__ b2,
    float* __restrict__ out)
{
    extern __shared__ __align__(16) __half smh[];
    __half* W1h = smh;                             // [128][FSTR]
    __half* Afb[2] = { smh + TILE_ELEMS, smh + 2 * TILE_ELEMS };
    float*  red = (float*)(smh + 3 * TILE_ELEMS);  // [2][128][2]

    const int tid  = threadIdx.x;
    const int lane = tid & 31, warp = tid >> 5;
    const int wm = (warp & 3) * 32;
    const int wn = (warp >> 2) * 64;
    const size_t tileBase = (size_t)blockIdx.x * NTILES;

    // prologue: W1 + feat tile0 (G0), feat tile1 (G1)
    {
#pragma unroll
        for (int i = 0; i < 8; i++) {
            int idx = i * 256 + tid;
            int row = idx >> 4, c8 = (idx & 15) * 8;
            cp_async16(&W1h[row * FSTR + c8], g_w1h + idx * 8);
        }
        const __half* f0 = g_feat + tileBase * 128 * D_;
#pragma unroll
        for (int i = 0; i < 8; i++) {
            int idx = i * 256 + tid;
            int row = idx >> 4, c8 = (idx & 15) * 8;
            cp_async16(&Afb[0][row * FSTR + c8], f0 + idx * 8);
        }
        asm volatile("cp.async.commit_group;\n" ::: "memory");
        const __half* f1 = f0 + 128 * D_;
#pragma unroll
        for (int i = 0; i < 8; i++) {
            int idx = i * 256 + tid;
            int row = idx >> 4, c8 = (idx & 15) * 8;
            cp_async16(&Afb[1][row * FSTR + c8], f1 + idx * 8);
        }
        asm volatile("cp.async.commit_group;\n" ::: "memory");
    }

    const uint32_t bbase = s2u(W1h);

#pragma unroll 1
    for (int t = 0; t < NTILES; t++) {
        if (t < NTILES - 1)
            asm volatile("cp.async.wait_group 1;\n" ::: "memory");
        else
            asm volatile("cp.async.wait_group 0;\n" ::: "memory");
        __syncthreads();

        const int ptBase = (int)(tileBase + t) * 128;
        const uint32_t abase = s2u(Afb[t & 1]);

        float acc[2][8][4];
#pragma unroll
        for (int mt = 0; mt < 2; mt++)
#pragma unroll
            for (int nt = 0; nt < 8; nt++)
#pragma unroll
                for (int q = 0; q < 4; q++) acc[mt][nt][q] = 0.f;

#pragma unroll
        for (int kc = 0; kc < 8; kc++) {
            int k0 = kc * 16;
            uint32_t af[2][4];
#pragma unroll
            for (int mt = 0; mt < 2; mt++) {
                int row = wm + mt * 16 + (lane & 15);
                int col = k0 + ((lane >> 4) << 3);
                ldm_x4(af[mt], abase + (row * FSTR + col) * 2);
            }
            uint32_t bf[8][2];
#pragma unroll
            for (int np = 0; np < 4; np++) {
                int n = wn + np * 16 + (lane & 7) + ((lane >> 4) << 3);
                int k = k0 + ((lane >> 3) & 1) * 8;
                uint32_t r[4];
                ldm_x4(r, bbase + (n * FSTR + k) * 2);
                bf[2 * np][0]     = r[0];  bf[2 * np][1]     = r[1];
                bf[2 * np + 1][0] = r[2];  bf[2 * np + 1][1] = r[3];
            }
#pragma unroll
            for (int mt = 0; mt < 2; mt++)
#pragma unroll
                for (int nt = 0; nt < 8; nt++)
                    mma_f16(acc[mt][nt], af[mt], bf[nt]);
        }

        // epilogue: relu(acc+b1), partial W2 @ h, shuffle-reduce over lane&3
        float2 b1v[8], w20v[8], w21v[8];
#pragma unroll
        for (int nt = 0; nt < 8; nt++) {
            int j = wn + nt * 8 + (lane & 3) * 2;
            b1v[nt]  = *(const float2*)&b1[j];
            w20v[nt] = *(const float2*)&W2[j];
            w21v[nt] = *(const float2*)&W2[128 + j];
        }
        float s0[2][2], s1[2][2];
#pragma unroll
        for (int mt = 0; mt < 2; mt++)
#pragma unroll
            for (int hh = 0; hh < 2; hh++) { s0[mt][hh] = 0.f; s1[mt][hh] = 0.f; }
#pragma unroll
        for (int mt = 0; mt < 2; mt++)
#pragma unroll
            for (int nt = 0; nt < 8; nt++) {
                float h00 = fmaxf(acc[mt][nt][0] + b1v[nt].x, 0.f);
                float h01 = fmaxf(acc[mt][nt][1] + b1v[nt].y, 0.f);
                float h10 = fmaxf(acc[mt][nt][2] + b1v[nt].x, 0.f);
                float h11 = fmaxf(acc[mt][nt][3] + b1v[nt].y, 0.f);
                s0[mt][0] = fmaf(w20v[nt].x, h00, s0[mt][0]);
                s0[mt][0] = fmaf(w20v[nt].y, h01, s0[mt][0]);
                s1[mt][0] = fmaf(w21v[nt].x, h00, s1[mt][0]);
                s1[mt][0] = fmaf(w21v[nt].y, h01, s1[mt][0]);
                s0[mt][1] = fmaf(w20v[nt].x, h10, s0[mt][1]);
                s0[mt][1] = fmaf(w20v[nt].y, h11, s0[mt][1]);
                s1[mt][1] = fmaf(w21v[nt].x, h10, s1[mt][1]);
                s1[mt][1] = fmaf(w21v[nt].y, h11, s1[mt][1]);
            }
#pragma unroll
        for (int mt = 0; mt < 2; mt++)
#pragma unroll
            for (int hh = 0; hh < 2; hh++) {
#pragma unroll
                for (int ofs = 1; ofs < 4; ofs <<= 1) {
                    s0[mt][hh] += __shfl_xor_sync(0xffffffffu, s0[mt][hh], ofs);
                    s1[mt][hh] += __shfl_xor_sync(0xffffffffu, s1[mt][hh], ofs);
                }
            }
        if ((lane & 3) == 0) {
            int gg = warp >> 2;
#pragma unroll
            for (int mt = 0; mt < 2; mt++)
#pragma unroll
                for (int hh = 0; hh < 2; hh++) {
                    int row = wm + mt * 16 + (lane >> 2) + 8 * hh;
                    red[(gg * 128 + row) * 2 + 0] = s0[mt][hh];
                    red[(gg * 128 + row) * 2 + 1] = s1[mt][hh];
                }
        }
        __syncthreads();   // all warps past mma loop & red written

        // prefetch feat tile t+2 into the buffer just freed (t&1)
        if (t < NTILES - 2) {
            const __half* fn = g_feat + (tileBase + t + 2) * 128 * D_;
#pragma unroll
            for (int i = 0; i < 8; i++) {
                int idx = i * 256 + tid;
                int row = idx >> 4, c8 = (idx & 15) * 8;
                cp_async16(&Afb[t & 1][row * FSTR + c8], fn + idx * 8);
            }
            asm volatile("cp.async.commit_group;\n" ::: "memory");
        }

        {
            int pt = tid >> 1, c = tid & 1;
            float s = b2[c] + red[pt * 2 + c] + red[(128 + pt) * 2 + c];
            float v = tanhf(s) * MAX_DELTA;
            int gi = (ptBase + pt) * 2 + c;
            out[gi] = coords[gi] + v;
        }
        __syncthreads();
    }
}

// ---------------------------------------------------------------------------
extern "C" void kernel_launch(void* const* d_in, const int* in_sizes, int n_in,
                              void* d_out, int out_size)
{
    (void)in_sizes; (void)n_in; (void)out_size;
    const float* fmap   = (const float*)d_in[0];
    const float* coords = (const float*)d_in[1];
    const float* Wp     = (const float*)d_in[2];
    const float* W1     = (const float*)d_in[3];
    const float* b1     = (const float*)d_in[4];
    const float* W2     = (const float*)d_in[5];
    const float* b2     = (const float*)d_in[6];
    float* out = (float*)d_out;

    wt_convert<<<48, 256>>>(Wp, W1);

    cudaFuncSetAttribute(proj_kernel,
                         cudaFuncAttributeMaxDynamicSharedMemorySize, PROJ_SMEM);
    proj_kernel<<<dim3(HW_ / 256, B_), 256, PROJ_SMEM>>>(fmap);

    sample_kernel<<<(B_ * T_) / 64, 256>>>(coords);

    cudaFuncSetAttribute(mlp_kernel,
                         cudaFuncAttributeMaxDynamicSharedMemorySize, MLP_SMEM);
    mlp_kernel<<<(B_ * T_) / (128 * NTILES), 256, MLP_SMEM>>>(coords, b1, W2, b2, out);
}

// round 9
// speedup vs baseline: 1.1315x; 1.0315x over previous
#include <cuda_runtime.h>
#include <cuda_bf16.h>
#include <cuda_fp16.h>
#include <math.h>
#include <stdint.h>

#define B_   4
#define C_   256
#define D_   128
#define HW_  16384
#define W_   128
#define T_   16384
#define MAX_DELTA 0.0009765625f   // 0.5/512

__device__ uint8_t g_vm8[(size_t)B_ * HW_ * D_];       // fp8 vm [b][pix][d]
__device__ __half g_feat[(size_t)B_ * T_ * D_];        // fp16 feat [pt][d]
__device__ __nv_bfloat16 g_wp[D_ * C_];                // bf16 Wp [d][c]
__device__ __half g_w1h[D_ * D_];                      // fp16 W1 [j][k]

// ---------------------------------------------------------------------------
__device__ __forceinline__ uint32_t s2u(const void* p) {
    return (uint32_t)__cvta_generic_to_shared(p);
}
__device__ __forceinline__ void cp_async16(void* smem_dst, const void* gmem_src) {
    asm volatile("cp.async.cg.shared.global [%0], [%1], 16;\n"
        :: "r"(s2u(smem_dst)), "l"(gmem_src));
}
__device__ __forceinline__ void ldm_x4(uint32_t r[4], uint32_t addr) {
    asm volatile("ldmatrix.sync.aligned.m8n8.x4.shared.b16 {%0,%1,%2,%3}, [%4];\n"
        : "=r"(r[0]), "=r"(r[1]), "=r"(r[2]), "=r"(r[3]) : "r"(addr));
}
__device__ __forceinline__ void ldm_x4t(uint32_t r[4], uint32_t addr) {
    asm volatile("ldmatrix.sync.aligned.m8n8.x4.trans.shared.b16 {%0,%1,%2,%3}, [%4];\n"
        : "=r"(r[0]), "=r"(r[1]), "=r"(r[2]), "=r"(r[3]) : "r"(addr));
}
__device__ __forceinline__ void mma_bf16(float c[4], const uint32_t a[4], const uint32_t b[2]) {
    asm volatile("mma.sync.aligned.m16n8k16.row.col.f32.bf16.bf16.f32 "
        "{%0,%1,%2,%3}, {%4,%5,%6,%7}, {%8,%9}, {%0,%1,%2,%3};\n"
        : "+f"(c[0]), "+f"(c[1]), "+f"(c[2]), "+f"(c[3])
        : "r"(a[0]), "r"(a[1]), "r"(a[2]), "r"(a[3]), "r"(b[0]), "r"(b[1]));
}
__device__ __forceinline__ void mma_f16(float c[4], const uint32_t a[4], const uint32_t b[2]) {
    asm volatile("mma.sync.aligned.m16n8k16.row.col.f32.f16.f16.f32 "
        "{%0,%1,%2,%3}, {%4,%5,%6,%7}, {%8,%9}, {%0,%1,%2,%3};\n"
        : "+f"(c[0]), "+f"(c[1]), "+f"(c[2]), "+f"(c[3])
        : "r"(a[0]), "r"(a[1]), "r"(a[2]), "r"(a[3]), "r"(b[0]), "r"(b[1]));
}
__device__ __forceinline__ uint16_t pack_e4m3x2(float lo, float hi) {
    uint16_t r;
    asm("cvt.rn.satfinite.e4m3x2.f32 %0, %1, %2;" : "=h"(r) : "f"(hi), "f"(lo));
    return r;
}
__device__ __forceinline__ __half2 e4m3x2_to_h2(uint32_t u) {
    uint32_t r;
    asm("cvt.rn.f16x2.e4m3x2 %0, %1;" : "=r"(r) : "h"((uint16_t)u));
    return *(__half2*)&r;
}

// smem layout constants for proj
#define ASTR 136
#define BSTR 264
#define BS_ELEMS  (128 * BSTR)
#define AST_ELEMS (32 * ASTR)
#define PROJ_SMEM ((BS_ELEMS + 2 * AST_ELEMS) * 2)   // 84992 bytes

// ---------------------------------------------------------------------------
// Kernel 0: one-time weight conversion.
// ---------------------------------------------------------------------------
__global__ __launch_bounds__(256) void wt_convert(const float* __restrict__ Wp,
                                                  const float* __restrict__ W1)
{
    int i = blockIdx.x * 256 + threadIdx.x;
    if (i < 8192) {
        float4 v = *(const float4*)&Wp[i * 4];
        __nv_bfloat162* dst = (__nv_bfloat162*)&g_wp[i * 4];
        dst[0] = __floats2bfloat162_rn(v.x, v.y);
        dst[1] = __floats2bfloat162_rn(v.z, v.w);
    } else {
        int j = i - 8192;
        float4 v = *(const float4*)&W1[j * 4];
        __half2* dst = (__half2*)&g_w1h[j * 4];
        dst[0] = __floats2half2_rn(v.x, v.y);
        dst[1] = __floats2half2_rn(v.z, v.w);
    }
}

// ---------------------------------------------------------------------------
// Kernel 1: projection GEMM -> fp8 vm. Persistent: 2 m-tiles per block,
// Wp loaded once per block (cp.async), fmap prefetch chain crosses tiles.
// ---------------------------------------------------------------------------
__global__ __launch_bounds__(256, 2) void proj_kernel(const float* __restrict__ fmap)
{
    extern __shared__ __align__(16) __nv_bfloat16 sm[];
    __nv_bfloat16* Bs  = sm;               // [128 n][BSTR k]
    __nv_bfloat16* AsT = sm + BS_ELEMS;    // [2 buf][32 k][ASTR m]

    const int b      = blockIdx.y;
    const int tid    = threadIdx.x;
    const int lane   = tid & 31, warp = tid >> 5;

    {
        const int row = tid >> 1;
        const int c0  = (tid & 1) * 16;
#pragma unroll
        for (int c = 0; c < 16; c++) {
            int chunk = c0 + c;
            cp_async16(&Bs[row * BSTR + chunk * 8], &g_wp[row * C_ + chunk * 8]);
        }
        asm volatile("cp.async.commit_group;\n" ::: "memory");
    }

    const int lk = tid >> 3;
    const int l8 = tid & 7;
    const float* fb = fmap + (size_t)b * C_ * HW_ + blockIdx.x * 256;

    float4 st[4];
#pragma unroll
    for (int j = 0; j < 4; j++)
        st[j] = *(const float4*)&fb[(size_t)lk * HW_ + (l8 + 8 * j) * 4];
    {
        __nv_bfloat16* A0 = AsT;
#pragma unroll
        for (int j = 0; j < 4; j++) {
            int m = (l8 + 8 * j) * 4;
            __nv_bfloat162* d2 = (__nv_bfloat162*)&A0[lk * ASTR + m];
            d2[0] = __floats2bfloat162_rn(st[j].x, st[j].y);
            d2[1] = __floats2bfloat162_rn(st[j].z, st[j].w);
        }
    }
    asm volatile("cp.async.wait_group 0;\n" ::: "memory");
    __syncthreads();

    const int wm = (warp & 3) * 32;
    const int wn = (warp >> 2) * 64;
    const uint32_t bbase = s2u(Bs);

    float acc[2][8][4];
#pragma unroll
    for (int mt = 0; mt < 2; mt++)
#pragma unroll
        for (int nt = 0; nt < 8; nt++)
#pragma unroll
            for (int q = 0; q < 4; q++) acc[mt][nt][q] = 0.f;

#pragma unroll 1
    for (int t = 0; t < 2; t++) {
#pragma unroll 1
        for (int kc = 0; kc < 8; kc++) {
            const int g = t * 8 + kc;
            if (g < 15) {
                const int gn = g + 1;
                const float* src = fb + (size_t)((gn & 7) * 32 + lk) * HW_ + ((gn >> 3) * 128);
#pragma unroll
                for (int j = 0; j < 4; j++)
                    st[j] = *(const float4*)&src[(l8 + 8 * j) * 4];
            }
            const uint32_t abase = s2u(AsT + (g & 1) * AST_ELEMS);

#pragma unroll
            for (int ks = 0; ks < 2; ks++) {
                uint32_t af[2][4];
#pragma unroll
                for (int mt = 0; mt < 2; mt++) {
                    int row = ks * 16 + (lane & 7) + ((lane >> 4) << 3);
                    int col = wm + mt * 16 + ((lane >> 3) & 1) * 8;
                    ldm_x4t(af[mt], abase + (row * ASTR + col) * 2);
                }
                uint32_t bf[8][2];
#pragma unroll
                for (int np = 0; np < 4; np++) {
                    int n = wn + np * 16 + (lane & 7) + ((lane >> 4) << 3);
                    int k = kc * 32 + ks * 16 + ((lane >> 3) & 1) * 8;
                    uint32_t r[4];
                    ldm_x4(r, bbase + (n * BSTR + k) * 2);
                    bf[2 * np][0]     = r[0];  bf[2 * np][1]     = r[1];
                    bf[2 * np + 1][0] = r[2];  bf[2 * np + 1][1] = r[3];
                }
#pragma unroll
                for (int mt = 0; mt < 2; mt++)
#pragma unroll
                    for (int nt = 0; nt < 8; nt++)
                        mma_bf16(acc[mt][nt], af[mt], bf[nt]);
            }

            if (g < 15) {
                __nv_bfloat16* An = AsT + ((g + 1) & 1) * AST_ELEMS;
#pragma unroll
                for (int j = 0; j < 4; j++) {
                    int m = (l8 + 8 * j) * 4;
                    __nv_bfloat162* d2 = (__nv_bfloat162*)&An[lk * ASTR + m];
                    d2[0] = __floats2bfloat162_rn(st[j].x, st[j].y);
                    d2[1] = __floats2bfloat162_rn(st[j].z, st[j].w);
                }
            }
            __syncthreads();
        }

        uint8_t* outp = g_vm8 + ((size_t)b * HW_ + blockIdx.x * 256 + t * 128) * D_;
#pragma unroll
        for (int mt = 0; mt < 2; mt++) {
#pragma unroll
            for (int nt = 0; nt < 8; nt++) {
                int r0 = wm + mt * 16 + (lane >> 2);
                int d0 = wn + nt * 8 + (lane & 3) * 2;
                *(uint16_t*)&outp[(size_t)r0 * D_ + d0] =
                    pack_e4m3x2(acc[mt][nt][0], acc[mt][nt][1]);
                *(uint16_t*)&outp[(size_t)(r0 + 8) * D_ + d0] =
                    pack_e4m3x2(acc[mt][nt][2], acc[mt][nt][3]);
                acc[mt][nt][0] = acc[mt][nt][1] = acc[mt][nt][2] = acc[mt][nt][3] = 0.f;
            }
        }
    }
}

// ---------------------------------------------------------------------------
// Kernel 2: branch-free 4x4 stencil sampler (R4 shape: warp/point, LDG.32).
// ---------------------------------------------------------------------------
__global__ __launch_bounds__(256, 4) void sample_kernel(const float* __restrict__ coords)
{
    const int tid  = threadIdx.x;
    const int lane = tid & 31, warp = tid >> 5;
    const int ptBase = blockIdx.x * 64 + warp * 8;
    const float inv9 = 1.f / 9.f;

#pragma unroll 1
    for (int i = 0; i < 8; i++) {
        int gpt = ptBase + i;
        int b   = gpt >> 14;

        float cx = coords[2 * gpt], cy = coords[2 * gpt + 1];
        float ix = cx * 127.f, iy = cy * 127.f;
        float xf = floorf(ix), yf = floorf(iy);
        int   x0 = (int)xf,    y0 = (int)yf;
        float fx = ix - xf,    fy = iy - yf;
        float Xw[4] = {1.f - fx, 1.f, 1.f, fx};
        float Yw[4] = {1.f - fy, 1.f, 1.f, fy};

        float wx[4], wy[4];
        int   px[4], py[4];
#pragma unroll
        for (int q = 0; q < 4; q++) {
            int x = x0 - 1 + q;
            bool vx = ((unsigned)x < 128u);
            wx[q] = vx ? Xw[q] : 0.f;
            px[q] = vx ? x : 0;
            int y = y0 - 1 + q;
            bool vy = ((unsigned)y < 128u);
            wy[q] = vy ? (Yw[q] * inv9) : 0.f;
            py[q] = vy ? y : 0;
        }

        const uint32_t* vmb = ((const uint32_t*)g_vm8) + (size_t)b * HW_ * 32 + lane;
        uint32_t off[16];
#pragma unroll
        for (int j = 0; j < 4; j++)
#pragma unroll
            for (int q = 0; q < 4; q++)
                off[j * 4 + q] = (uint32_t)(py[j] * W_ + px[q]) * 32u;

        uint32_t v[16];
#pragma unroll
        for (int t = 0; t < 16; t++) v[t] = vmb[off[t]];

        __half2 a01 = __half2(__float2half(0.f), __float2half(0.f));
        __half2 a23 = a01;
#pragma unroll
        for (int j = 0; j < 4; j++)
#pragma unroll
            for (int q = 0; q < 4; q++) {
                int t = j * 4 + q;
                __half2 w2 = __float2half2_rn(wy[j] * wx[q]);
                a01 = __hfma2(e4m3x2_to_h2(v[t] & 0xffffu), w2, a01);
                a23 = __hfma2(e4m3x2_to_h2(v[t] >> 16), w2, a23);
            }

        uint2 pk;
        pk.x = *(uint32_t*)&a01;
        pk.y = *(uint32_t*)&a23;
        *(uint2*)&g_feat[(size_t)gpt * D_ + lane * 4] = pk;
    }
}

// ---------------------------------------------------------------------------
// Kernel 3: MLP GEMM, 2 tiles per block, 2 CTAs/SM (128-reg cap).
// W1 loaded once per block; both feat tiles async-loaded in prologue.
// ---------------------------------------------------------------------------
#define FSTR 136
#define TILE_ELEMS (128 * FSTR)
#define MLP_SMEM ((3 * TILE_ELEMS) * 2 + 2 * 128 * 2 * 4)   // 106496 B
#define NTILES 2

__global__ __launch_bounds__(256, 2) void mlp_kernel(
    const float* __restrict__ coords, const float* __restrict__ b1,
    const float* __restrict__ W2,     const float* __restrict__ b2,
    float* __restrict__ out)
{
    extern __shared__ __align__(16) __half smh[];
    __half* W1h = smh;                             // [128][FSTR]
    __half* Af0 = smh + TILE_ELEMS;
    __half* Af1 = smh + 2 * TILE_ELEMS;
    float*  red = (float*)(smh + 3 * TILE_ELEMS);  // [2][128][2]

    const int tid  = threadIdx.x;
    const int lane = tid & 31, warp = tid >> 5;
    const int wm = (warp & 3) * 32;
    const int wn = (warp >> 2) * 64;
    const size_t tileBase = (size_t)blockIdx.x * NTILES;

    // prologue: W1 + feat tile0 (G0), feat tile1 (G1)
    {
#pragma unroll
        for (int i = 0; i < 8; i++) {
            int idx = i * 256 + tid;
            int row = idx >> 4, c8 = (idx & 15) * 8;
            cp_async16(&W1h[row * FSTR + c8], g_w1h + idx * 8);
        }
        const __half* f0 = g_feat + tileBase * 128 * D_;
#pragma unroll
        for (int i = 0; i < 8; i++) {
            int idx = i * 256 + tid;
            int row = idx >> 4, c8 = (idx & 15) * 8;
            cp_async16(&Af0[row * FSTR + c8], f0 + idx * 8);
        }
        asm volatile("cp.async.commit_group;\n" ::: "memory");
        const __half* f1 = f0 + 128 * D_;
#pragma unroll
        for (int i = 0; i < 8; i++) {
            int idx = i * 256 + tid;
            int row = idx >> 4, c8 = (idx & 15) * 8;
            cp_async16(&Af1[row * FSTR + c8], f1 + idx * 8);
        }
        asm volatile("cp.async.commit_group;\n" ::: "memory");
    }

    const uint32_t bbase = s2u(W1h);

#pragma unroll 1
    for (int t = 0; t < NTILES; t++) {
        if (t == 0)
            asm volatile("cp.async.wait_group 1;\n" ::: "memory");
        else
            asm volatile("cp.async.wait_group 0;\n" ::: "memory");
        __syncthreads();

        const int ptBase = (int)(tileBase + t) * 128;
        const uint32_t abase = s2u(t ? Af1 : Af0);

        float acc[2][8][4];
#pragma unroll
        for (int mt = 0; mt < 2; mt++)
#pragma unroll
            for (int nt = 0; nt < 8; nt++)
#pragma unroll
                for (int q = 0; q < 4; q++) acc[mt][nt][q] = 0.f;

#pragma unroll
        for (int kc = 0; kc < 8; kc++) {
            int k0 = kc * 16;
            uint32_t af[2][4];
#pragma unroll
            for (int mt = 0; mt < 2; mt++) {
                int row = wm + mt * 16 + (lane & 15);
                int col = k0 + ((lane >> 4) << 3);
                ldm_x4(af[mt], abase + (row * FSTR + col) * 2);
            }
            uint32_t bf[8][2];
#pragma unroll
            for (int np = 0; np < 4; np++) {
                int n = wn + np * 16 + (lane & 7) + ((lane >> 4) << 3);
                int k = k0 + ((lane >> 3) & 1) * 8;
                uint32_t r[4];
                ldm_x4(r, bbase + (n * FSTR + k) * 2);
                bf[2 * np][0]     = r[0];  bf[2 * np][1]     = r[1];
                bf[2 * np + 1][0] = r[2];  bf[2 * np + 1][1] = r[3];
            }
#pragma unroll
            for (int mt = 0; mt < 2; mt++)
#pragma unroll
                for (int nt = 0; nt < 8; nt++)
                    mma_f16(acc[mt][nt], af[mt], bf[nt]);
        }

        // epilogue: relu(acc+b1), partial W2 @ h, shuffle-reduce over lane&3
        float2 b1v[8], w20v[8], w21v[8];
#pragma unroll
        for (int nt = 0; nt < 8; nt++) {
            int j = wn + nt * 8 + (lane & 3) * 2;
            b1v[nt]  = *(const float2*)&b1[j];
            w20v[nt] = *(const float2*)&W2[j];
            w21v[nt] = *(const float2*)&W2[128 + j];
        }
        float s0[2][2], s1[2][2];
#pragma unroll
        for (int mt = 0; mt < 2; mt++)
#pragma unroll
            for (int hh = 0; hh < 2; hh++) { s0[mt][hh] = 0.f; s1[mt][hh] = 0.f; }
#pragma unroll
        for (int mt = 0; mt < 2; mt++)
#pragma unroll
            for (int nt = 0; nt < 8; nt++) {
                float h00 = fmaxf(acc[mt][nt][0] + b1v[nt].x, 0.f);
                float h01 = fmaxf(acc[mt][nt][1] + b1v[nt].y, 0.f);
                float h10 = fmaxf(acc[mt][nt][2] + b1v[nt].x, 0.f);
                float h11 = fmaxf(acc[mt][nt][3] + b1v[nt].y, 0.f);
                s0[mt][0] = fmaf(w20v[nt].x, h00, s0[mt][0]);
                s0[mt][0] = fmaf(w20v[nt].y, h01, s0[mt][0]);
                s1[mt][0] = fmaf(w21v[nt].x, h00, s1[mt][0]);
                s1[mt][0] = fmaf(w21v[nt].y, h01, s1[mt][0]);
                s0[mt][1] = fmaf(w20v[nt].x, h10, s0[mt][1]);
                s0[mt][1] = fmaf(w20v[nt].y, h11, s0[mt][1]);
                s1[mt][1] = fmaf(w21v[nt].x, h10, s1[mt][1]);
                s1[mt][1] = fmaf(w21v[nt].y, h11, s1[mt][1]);
            }
#pragma unroll
        for (int mt = 0; mt < 2; mt++)
#pragma unroll
            for (int hh = 0; hh < 2; hh++) {
#pragma unroll
                for (int ofs = 1; ofs < 4; ofs <<= 1) {
                    s0[mt][hh] += __shfl_xor_sync(0xffffffffu, s0[mt][hh], ofs);
                    s1[mt][hh] += __shfl_xor_sync(0xffffffffu, s1[mt][hh], ofs);
                }
            }
        if ((lane & 3) == 0) {
            int gg = warp >> 2;
#pragma unroll
            for (int mt = 0; mt < 2; mt++)
#pragma unroll
                for (int hh = 0; hh < 2; hh++) {
                    int row = wm + mt * 16 + (lane >> 2) + 8 * hh;
                    red[(gg * 128 + row) * 2 + 0] = s0[mt][hh];
                    red[(gg * 128 + row) * 2 + 1] = s1[mt][hh];
                }
        }
        __syncthreads();

        {
            int pt = tid >> 1, c = tid & 1;
            float s = b2[c] + red[pt * 2 + c] + red[(128 + pt) * 2 + c];
            float v = tanhf(s) * MAX_DELTA;
            int gi = (ptBase + pt) * 2 + c;
            out[gi] = coords[gi] + v;
        }
        if (t == 0) __syncthreads();
    }
}

// ---------------------------------------------------------------------------
extern "C" void kernel_launch(void* const* d_in, const int* in_sizes, int n_in,
                              void* d_out, int out_size)
{
    (void)in_sizes; (void)n_in; (void)out_size;
    const float* fmap   = (const float*)d_in[0];
    const float* coords = (const float*)d_in[1];
    const float* Wp     = (const float*)d_in[2];
    const float* W1     = (const float*)d_in[3];
    const float* b1     = (const float*)d_in[4];
    const float* W2     = (const float*)d_in[5];
    const float* b2     = (const float*)d_in[6];
    float* out = (float*)d_out;

    wt_convert<<<48, 256>>>(Wp, W1);

    cudaFuncSetAttribute(proj_kernel,
                         cudaFuncAttributeMaxDynamicSharedMemorySize, PROJ_SMEM);
    proj_kernel<<<dim3(HW_ / 256, B_), 256, PROJ_SMEM>>>(fmap);

    sample_kernel<<<(B_ * T_) / 64, 256>>>(coords);

    cudaFuncSetAttribute(mlp_kernel,
                         cudaFuncAttributeMaxDynamicSharedMemorySize, MLP_SMEM);
    mlp_kernel<<<(B_ * T_) / (128 * NTILES), 256, MLP_SMEM>>>(coords, b1, W2, b2, out);
}